// round 14
// baseline (speedup 1.0000x reference)
#include <cuda_runtime.h>
#include <cstdint>

// SparseToDense: counting sort to 32K (b,x,y/2) bins. Reorder copies the
// 64B feature payload into sorted order (random writes absorbed by L2, which
// the ~98MB sorted array nearly fits), so the scatter kernel does ONLY
// sequential reads + sequential (bulk-async) writes. Singles use plain STS,
// multi-occupancy voxels use smem atomics.
// out[b][f][x][y][z] += feats[n][f], out = (4,16,128,128,128) f32.

#define VOL    (128 * 128 * 128)
#define FEATS  16
#define NBINS  32768            // (b:2, x:7, y/2:6)
#define NMAX   2100000
#define BLKV   256              // voxels per bin
#define BLKT   128              // threads per scatter CTA

__device__ int g_bins[NBINS];        // zero at load; scan re-zeroes each call
__device__ int g_start[NBINS + 1];
__device__ unsigned g_pinfo[NMAX];   // bin:15 | local:8 | rank:9 ; ~0u invalid
__device__ float4 g_fsorted[NMAX * 4]; // sorted 64B feature payloads
__device__ unsigned char g_slocal[NMAX]; // sorted local voxel ids

__device__ __forceinline__ bool decode(const int4 c, unsigned& bin, unsigned& local)
{
    const unsigned x = (unsigned)c.y;
    const unsigned y = (unsigned)c.z;
    const unsigned z = (unsigned)c.w;
    if ((x >= 128u) | (y >= 128u) | (z >= 128u)) return false;
    bin   = ((((unsigned)c.x << 7) | x) << 6) | (y >> 1);   // (b,x,y/2)
    local = ((y & 1u) << 7) | z;                            // 0..255
    return true;
}

// Histogram; atomicAdd return value is the point's rank within its bin.
__global__ void __launch_bounds__(256)
hist_kernel(const int4* __restrict__ coords, int n)
{
    for (int i = blockIdx.x * blockDim.x + threadIdx.x; i < n;
         i += gridDim.x * blockDim.x) {
        unsigned bin, local;
        if (decode(__ldg(&coords[i]), bin, local)) {
            unsigned rank = atomicAdd(&g_bins[bin], 1);   // rank < 512 always
            g_pinfo[i] = (bin << 17) | (local << 9) | rank;
        } else {
            g_pinfo[i] = ~0u;
        }
    }
}

// Exclusive scan of 32K bins; restores g_bins to zero for the next call.
__global__ void __launch_bounds__(1024)
scan_kernel()
{
    __shared__ int s[1024];
    const int t = threadIdx.x;
    int v[32];
    int sum = 0;
    #pragma unroll
    for (int k = 0; k < 8; k++) {
        int4 q = ((const int4*)g_bins)[t * 8 + k];
        v[4*k+0] = q.x; v[4*k+1] = q.y; v[4*k+2] = q.z; v[4*k+3] = q.w;
        sum += q.x + q.y + q.z + q.w;
    }
    #pragma unroll
    for (int k = 0; k < 8; k++)
        ((int4*)g_bins)[t * 8 + k] = make_int4(0, 0, 0, 0);
    s[t] = sum;
    __syncthreads();
    for (int off = 1; off < 1024; off <<= 1) {
        int x = (t >= off) ? s[t - off] : 0;
        __syncthreads();
        s[t] += x;
        __syncthreads();
    }
    int run = s[t] - sum;
    #pragma unroll
    for (int k = 0; k < 8; k++) {
        int4 o;
        o.x = run;            o.y = run + v[4*k];
        o.z = o.y + v[4*k+1]; o.w = o.z + v[4*k+2];
        run = o.w + v[4*k+3];
        ((int4*)g_start)[t * 8 + k] = o;
    }
    if (t == 1023) g_start[NBINS] = run;
}

// Payload sort: sequential feat reads, L2-absorbed scattered writes.
__global__ void __launch_bounds__(256)
reorder_kernel(const float4* __restrict__ feats, int n)
{
    for (int i = blockIdx.x * blockDim.x + threadIdx.x; i < n;
         i += gridDim.x * blockDim.x) {
        const unsigned p = g_pinfo[i];
        if (p != ~0u) {
            const unsigned bin   = p >> 17;
            const unsigned local = (p >> 9) & 255u;
            const unsigned rank  = p & 511u;
            const int pos = g_start[bin] + (int)rank;

            const float4* fp = feats + (size_t)i * 4;
            float4 f0 = __ldg(fp + 0);
            float4 f1 = __ldg(fp + 1);
            float4 f2 = __ldg(fp + 2);
            float4 f3 = __ldg(fp + 3);
            float4* dst = g_fsorted + (size_t)pos * 4;
            dst[0] = f0; dst[1] = f1; dst[2] = f2; dst[3] = f3;
            g_slocal[pos] = (unsigned char)local;
        }
    }
}

__global__ void __launch_bounds__(BLKT)
scatter_kernel(float* __restrict__ out)
{
    __shared__ __align__(16) float acc[FEATS * BLKV];   // [f][256], 1KB per f
    __shared__ int cnt[BLKV];

    const unsigned bin = blockIdx.x;
    const int tid = threadIdx.x;
    const int start = g_start[bin];
    const int end   = g_start[bin + 1];
    const int npts  = end - start;

    #pragma unroll
    for (int k = 0; k < FEATS * BLKV / 4 / BLKT; k++)   // 8 iters
        *(float4*)&acc[(k * BLKT + tid) * 4] = make_float4(0.f, 0.f, 0.f, 0.f);
    cnt[2 * tid]     = 0;
    cnt[2 * tid + 1] = 0;

    if (npts <= BLKT) {
        // ---- fused single-pass: loads in flight across the count barrier ----
        const int t = start + tid;
        const bool have = (t < end);
        unsigned local = 0;
        float4 f0, f1, f2, f3;
        if (have) {
            local = g_slocal[t];
            const float4* fp = g_fsorted + (size_t)t * 4;   // sequential!
            f0 = __ldg(fp + 0);
            f1 = __ldg(fp + 1);
            f2 = __ldg(fp + 2);
            f3 = __ldg(fp + 3);
        }
        __syncthreads();                 // cnt[] zeros visible
        if (have) atomicAdd(&cnt[local], 1);
        __syncthreads();

        if (have) {
            float v[16] = { f0.x, f0.y, f0.z, f0.w,
                            f1.x, f1.y, f1.z, f1.w,
                            f2.x, f2.y, f2.z, f2.w,
                            f3.x, f3.y, f3.z, f3.w };
            if (cnt[local] == 1) {
                #pragma unroll
                for (int f = 0; f < FEATS; f++)
                    acc[f * BLKV + local] = v[f];
            } else {
                #pragma unroll
                for (int f = 0; f < FEATS; f++)
                    atomicAdd(&acc[f * BLKV + local], v[f]);
            }
        }
    } else {
        // ---- fallback two-pass (statistically unreachable; kept for safety) ----
        __syncthreads();
        for (int t = start + tid; t < end; t += BLKT)
            atomicAdd(&cnt[g_slocal[t]], 1);
        __syncthreads();
        for (int t = start + tid; t < end; t += BLKT) {
            const unsigned local = g_slocal[t];
            const float4* fp = g_fsorted + (size_t)t * 4;
            float4 f0 = __ldg(fp + 0);
            float4 f1 = __ldg(fp + 1);
            float4 f2 = __ldg(fp + 2);
            float4 f3 = __ldg(fp + 3);
            float v[16] = { f0.x, f0.y, f0.z, f0.w,
                            f1.x, f1.y, f1.z, f1.w,
                            f2.x, f2.y, f2.z, f2.w,
                            f3.x, f3.y, f3.z, f3.w };
            if (cnt[local] == 1) {
                #pragma unroll
                for (int f = 0; f < FEATS; f++)
                    acc[f * BLKV + local] = v[f];
            } else {
                #pragma unroll
                for (int f = 0; f < FEATS; f++)
                    atomicAdd(&acc[f * BLKV + local], v[f]);
            }
        }
    }
    __syncthreads();

    // ---- bulk async writeback: 16 contiguous 1KB chunks, TMA engine ----
    if (tid == 0) {
        asm volatile("fence.proxy.async.shared::cta;" ::: "memory");

        const unsigned b = bin >> 13;
        float* base = out + (size_t)b * FEATS * VOL + ((size_t)(bin & 8191u) << 8);

        uint32_t sa;
        asm("{ .reg .u64 t; cvta.to.shared.u64 t, %1; cvt.u32.u64 %0, t; }"
            : "=r"(sa) : "l"(acc));

        #pragma unroll
        for (int f = 0; f < FEATS; f++) {
            asm volatile(
                "cp.async.bulk.global.shared::cta.bulk_group [%0], [%1], %2;"
                :: "l"(base + (size_t)f * VOL),
                   "r"(sa + f * BLKV * 4),
                   "n"(BLKV * 4)
                : "memory");
        }
        asm volatile("cp.async.bulk.commit_group;" ::: "memory");
        asm volatile("cp.async.bulk.wait_group.read 0;" ::: "memory");
    }
}

extern "C" void kernel_launch(void* const* d_in, const int* in_sizes, int n_in,
                              void* d_out, int out_size)
{
    const int4*   coords = (const int4*)d_in[0];
    const float4* feats  = (const float4*)d_in[1];
    float*        out    = (float*)d_out;

    const int n = in_sizes[0] / 4;

    hist_kernel<<<1024, 256>>>(coords, n);       // launch 1
    scan_kernel<<<1, 1024>>>();                  // launch 2 (re-zeroes g_bins)
    reorder_kernel<<<1024, 256>>>(feats, n);     // launch 3 (payload sort)
    scatter_kernel<<<NBINS, BLKT>>>(out);        // launch 4  <- ncu capture slot
}

// round 15
// speedup vs baseline: 1.1294x; 1.1294x over previous
#include <cuda_runtime.h>
#include <cstdint>

// SparseToDense via single-pass fixed-capacity bucket partition (no histogram,
// no scan): pos = atomicAdd(cnt[bin]) indexes a CAP-slot payload region per
// bin. Scatter reads its bin's slots fully coalesced, count-gated smem
// accumulate, cp.async.bulk writeback. Overflow (>CAP pts/bin, ~impossible)
// handled correctly via a post-pass with red.global.add.
// out[b][f][x][y][z] += feats[n][f], out = (4,16,128,128,128) f32.

#define VOL    (128 * 128 * 128)
#define FEATS  16
#define NBINS  32768            // (b:2, x:7, y/2:6)
#define BLKV   256              // voxels per bin
#define BLKT   128              // threads per scatter CTA
#define CAP    128              // slots per bin (mean 46.7, sigma 6.8 -> 12 sigma)
#define OVMAX  65536

__device__ int g_cnt[NBINS];              // zero at load; scatter re-zeroes
__device__ int g_ovcnt;                   // zero at load; overflow re-zeroes
__device__ int g_ovlist[OVMAX];
__device__ float4 g_fslot[(size_t)NBINS * CAP * 4];   // 268MB slot payloads
__device__ unsigned char g_local[(size_t)NBINS * CAP];

__device__ __forceinline__ bool decode(const int4 c, unsigned& bin, unsigned& local)
{
    const unsigned x = (unsigned)c.y;
    const unsigned y = (unsigned)c.z;
    const unsigned z = (unsigned)c.w;
    if ((x >= 128u) | (y >= 128u) | (z >= 128u)) return false;
    bin   = ((((unsigned)c.x << 7) | x) << 6) | (y >> 1);   // (b,x,y/2)
    local = ((y & 1u) << 7) | z;                            // 0..255
    return true;
}

// Single-pass partition: coords+feats streamed sequentially, payload dropped
// into its bin slot. Replaces hist + scan + reorder.
__global__ void __launch_bounds__(256)
partition_kernel(const int4* __restrict__ coords,
                 const float4* __restrict__ feats, int n)
{
    for (int i = blockIdx.x * blockDim.x + threadIdx.x; i < n;
         i += gridDim.x * blockDim.x) {
        unsigned bin, local;
        if (!decode(__ldg(&coords[i]), bin, local)) continue;

        const int pos = atomicAdd(&g_cnt[bin], 1);
        if (pos < CAP) {
            const size_t s = (size_t)bin * CAP + pos;
            const float4* fp = feats + (size_t)i * 4;
            float4 f0 = __ldg(fp + 0);
            float4 f1 = __ldg(fp + 1);
            float4 f2 = __ldg(fp + 2);
            float4 f3 = __ldg(fp + 3);
            float4* dst = g_fslot + s * 4;
            dst[0] = f0; dst[1] = f1; dst[2] = f2; dst[3] = f3;
            g_local[s] = (unsigned char)local;
        } else {
            const int ov = atomicAdd(&g_ovcnt, 1);
            if (ov < OVMAX) g_ovlist[ov] = i;
        }
    }
}

__global__ void __launch_bounds__(BLKT)
scatter_kernel(float* __restrict__ out)
{
    __shared__ __align__(16) float acc[FEATS * BLKV];   // [f][256], 1KB per f
    __shared__ int cnt[BLKV];

    const unsigned bin = blockIdx.x;
    const int tid = threadIdx.x;
    int npts = g_cnt[bin];
    if (npts > CAP) npts = CAP;          // overflow points applied later

    #pragma unroll
    for (int k = 0; k < FEATS * BLKV / 4 / BLKT; k++)   // 8 iters
        *(float4*)&acc[(k * BLKT + tid) * 4] = make_float4(0.f, 0.f, 0.f, 0.f);
    cnt[2 * tid]     = 0;
    cnt[2 * tid + 1] = 0;

    // Fused single-pass (npts <= CAP == BLKT always): loads issued before the
    // count barrier; slot reads are fully coalesced within the bin region.
    const bool have = (tid < npts);
    unsigned local = 0;
    float4 f0, f1, f2, f3;
    if (have) {
        const size_t s = (size_t)bin * CAP + tid;
        local = g_local[s];
        const float4* fp = g_fslot + s * 4;
        f0 = __ldg(fp + 0);
        f1 = __ldg(fp + 1);
        f2 = __ldg(fp + 2);
        f3 = __ldg(fp + 3);
    }
    __syncthreads();                     // cnt[] zeros visible
    if (have) atomicAdd(&cnt[local], 1);
    __syncthreads();

    if (have) {
        float v[16] = { f0.x, f0.y, f0.z, f0.w,
                        f1.x, f1.y, f1.z, f1.w,
                        f2.x, f2.y, f2.z, f2.w,
                        f3.x, f3.y, f3.z, f3.w };
        if (cnt[local] == 1) {
            #pragma unroll
            for (int f = 0; f < FEATS; f++)
                acc[f * BLKV + local] = v[f];
        } else {
            #pragma unroll
            for (int f = 0; f < FEATS; f++)
                atomicAdd(&acc[f * BLKV + local], v[f]);
        }
    }
    __syncthreads();

    // ---- bulk async writeback: 16 contiguous 1KB chunks, TMA engine ----
    if (tid == 0) {
        asm volatile("fence.proxy.async.shared::cta;" ::: "memory");

        const unsigned b = bin >> 13;
        float* base = out + (size_t)b * FEATS * VOL + ((size_t)(bin & 8191u) << 8);

        uint32_t sa;
        asm("{ .reg .u64 t; cvta.to.shared.u64 t, %1; cvt.u32.u64 %0, t; }"
            : "=r"(sa) : "l"(acc));

        #pragma unroll
        for (int f = 0; f < FEATS; f++) {
            asm volatile(
                "cp.async.bulk.global.shared::cta.bulk_group [%0], [%1], %2;"
                :: "l"(base + (size_t)f * VOL),
                   "r"(sa + f * BLKV * 4),
                   "n"(BLKV * 4)
                : "memory");
        }
        asm volatile("cp.async.bulk.commit_group;" ::: "memory");
        asm volatile("cp.async.bulk.wait_group.read 0;" ::: "memory");

        g_cnt[bin] = 0;                  // clean for next graph replay
    }
}

// Apply overflow points (normally zero) with fire-and-forget atomics on the
// already-written dense output; then reset the overflow counter.
__global__ void __launch_bounds__(256)
overflow_kernel(const int4* __restrict__ coords,
                const float4* __restrict__ feats, float* __restrict__ out)
{
    const int tid = threadIdx.x;
    int nov = g_ovcnt;
    if (nov > OVMAX) nov = OVMAX;

    for (int t = tid; t < nov; t += 256) {
        const int i = g_ovlist[t];
        const int4 c = __ldg(&coords[i]);
        const unsigned lin = ((unsigned)c.y << 14) | ((unsigned)c.z << 7) | (unsigned)c.w;
        float* base = out + (size_t)c.x * (FEATS * (size_t)VOL) + lin;

        const float4* fp = feats + (size_t)i * 4;
        float4 f0 = __ldg(fp + 0);
        float4 f1 = __ldg(fp + 1);
        float4 f2 = __ldg(fp + 2);
        float4 f3 = __ldg(fp + 3);
        float v[16] = { f0.x, f0.y, f0.z, f0.w,
                        f1.x, f1.y, f1.z, f1.w,
                        f2.x, f2.y, f2.z, f2.w,
                        f3.x, f3.y, f3.z, f3.w };
        #pragma unroll
        for (int f = 0; f < FEATS; f++)
            asm volatile("red.global.add.f32 [%0], %1;"
                         :: "l"(base + (size_t)f * VOL), "f"(v[f]) : "memory");
    }
    __syncthreads();
    if (tid == 0) g_ovcnt = 0;           // clean for next graph replay
}

extern "C" void kernel_launch(void* const* d_in, const int* in_sizes, int n_in,
                              void* d_out, int out_size)
{
    const int4*   coords = (const int4*)d_in[0];
    const float4* feats  = (const float4*)d_in[1];
    float*        out    = (float*)d_out;

    const int n = in_sizes[0] / 4;

    partition_kernel<<<1024, 256>>>(coords, feats, n);  // launch 1
    scatter_kernel<<<NBINS, BLKT>>>(out);               // launch 2
    overflow_kernel<<<1, 256>>>(coords, feats, out);    // launch 3
}